// round 2
// baseline (speedup 1.0000x reference)
#include <cuda_runtime.h>
#include <cuda_bf16.h>
#include <cstdint>

// Problem constants (fixed shapes: [16, 4096, 2] fp32 both inputs)
#define NOBJ 16
#define P    4096
#define BM   128      // rows (set1) per CTA
#define BN   128      // cols (set2) per chunk
#define TM   8
#define TN   8
#define EPSF 1e-12f
#define FLTMAX_BITS 0x7F7FFFFF

// Scratch (no allocations allowed): col-min bits, per-(n,tile) row sums, mask partials
static __device__ int   g_colmin[NOBJ * P];
static __device__ float g_rowsum[NOBJ * 32];
static __device__ float g_maskpart[256];   // [n][chunk] chunk = 256 cols

// ---------------------------------------------------------------------------
// Kernel 1: init colmin to +FLT_MAX and compute per-block partial sums of set2
// grid = 256 blocks x 256 threads; block b covers 256 consecutive (n,j) slots
// ---------------------------------------------------------------------------
__global__ void k_init(const float* __restrict__ pt2) {
    __shared__ float sred[256];
    const int tid = threadIdx.x;
    const int idx = blockIdx.x * 256 + tid;      // 0 .. 65535 == n*4096 + j
    g_colmin[idx] = FLTMAX_BITS;
    float2 p = reinterpret_cast<const float2*>(pt2)[idx];
    sred[tid] = p.x + p.y;
    __syncthreads();
    #pragma unroll
    for (int s = 128; s > 0; s >>= 1) {
        if (tid < s) sred[tid] += sred[tid + s];
        __syncthreads();
    }
    if (tid == 0) g_maskpart[blockIdx.x] = sred[0];
}

// ---------------------------------------------------------------------------
// Kernel 2: main chamfer tiles.
// grid = (32 tiles, 16 objects), 256 threads (tx = tid&15, ty = tid>>4)
// Each thread: TM=8 rows (persistent row-mins on u), TN=8 cols per chunk.
// Column assignment c = jj*16 + tx  -> conflict-free LDS broadcast.
// d^2 = x2_i + u_ij ;  u_ij = y2_j - 2 x_i . y_j  (2 FFMA)
// Row ty*8+ii is shared across the 16 tx lanes of the ty group -> the row-min
// must be shuffle-reduced across those lanes before the final row sum.
// ---------------------------------------------------------------------------
__global__ __launch_bounds__(256) void k_main(const float* __restrict__ pt1,
                                              const float* __restrict__ pt2) {
    const int n    = blockIdx.y;
    const int tile = blockIdx.x;
    const int tid  = threadIdx.x;
    const int tx   = tid & 15;
    const int ty   = tid >> 4;

    __shared__ float  sA[BN], sB[BN], sY2[BN];
    __shared__ float2 sX[BM];
    __shared__ float  sRed[16 * 132];   // padded rows; also reused for final sum

    // load x tile (128 points of set1)
    const float2* p1 = reinterpret_cast<const float2*>(pt1) + n * P + tile * BM;
    if (tid < BM) sX[tid] = p1[tid];
    __syncthreads();

    float m2a[TM], m2b[TM], x2r[TM], rmin[TM];
    #pragma unroll
    for (int ii = 0; ii < TM; ii++) {
        float2 x = sX[ty * TM + ii];
        m2a[ii]  = -2.0f * x.x;
        m2b[ii]  = -2.0f * x.y;
        x2r[ii]  = fmaf(x.x, x.x, x.y * x.y);
        rmin[ii] = 3.402823466e38f;
    }

    const float2* p2 = reinterpret_cast<const float2*>(pt2) + n * P;

    for (int jc = 0; jc < P / BN; jc++) {
        __syncthreads();   // protects sA/sB/sY2 and sRed from previous chunk
        if (tid < BN) {
            float2 y = p2[jc * BN + tid];
            sA[tid]  = y.x;
            sB[tid]  = y.y;
            sY2[tid] = fmaf(y.x, y.x, y.y * y.y);
        }
        __syncthreads();

        #pragma unroll
        for (int jj = 0; jj < TN; jj++) {
            const int c = jj * 16 + tx;        // conflict-free: lane stride 4B
            const float ya = sA[c];
            const float yb = sB[c];
            const float yy = sY2[c];
            float cm = 3.402823466e38f;
            #pragma unroll
            for (int ii = 0; ii < TM; ii++) {
                float u = fmaf(m2a[ii], ya, yy);
                u       = fmaf(m2b[ii], yb, u);
                rmin[ii] = fminf(rmin[ii], u);          // row-min on u (shift-invariant)
                cm       = fminf(cm, u + x2r[ii]);      // col needs full d^2
            }
            sRed[ty * 132 + c] = cm;
        }
        __syncthreads();

        if (tid < BN) {
            float v = sRed[tid];
            #pragma unroll
            for (int t = 1; t < 16; t++) v = fminf(v, sRed[t * 132 + tid]);
            v = fmaxf(v, 0.0f);   // matches reference clip; enables int-ordered atomic
            atomicMin(&g_colmin[(n << 12) + jc * BN + tid], __float_as_int(v));
        }
    }

    // finalize row mins: reduce rmin across the 16 tx lanes of each ty group
    // (lanes 0-15 and 16-31 of a warp are exactly one ty group each -> width=16)
    float rs = 0.0f;
    #pragma unroll
    for (int ii = 0; ii < TM; ii++) {
        float r = rmin[ii];
        #pragma unroll
        for (int off = 8; off >= 1; off >>= 1)
            r = fminf(r, __shfl_xor_sync(0xffffffffu, r, off, 16));
        if (tx == 0) rs += sqrtf(fmaxf(x2r[ii] + r, EPSF));
    }
    __syncthreads();             // before reusing sRed as reduction buffer
    sRed[tid] = (tx == 0) ? rs : 0.0f;
    __syncthreads();
    #pragma unroll
    for (int s = 128; s > 0; s >>= 1) {
        if (tid < s) sRed[tid] += sRed[tid + s];
        __syncthreads();
    }
    if (tid == 0) g_rowsum[n * 32 + tile] = sRed[0];
}

// ---------------------------------------------------------------------------
// Kernel 3: finalize. 1 block x 256 threads.
// ---------------------------------------------------------------------------
__global__ void k_final(float* __restrict__ out) {
    __shared__ float sred[256];
    __shared__ float s_total;
    const int tid = threadIdx.x;
    if (tid == 0) s_total = 0.0f;

    for (int n = 0; n < NOBJ; n++) {
        float s = 0.0f;
        for (int j = tid; j < P; j += 256) {
            float v = __int_as_float(g_colmin[(n << 12) + j]);
            s += sqrtf(fmaxf(v, EPSF));
        }
        __syncthreads();
        sred[tid] = s;
        __syncthreads();
        #pragma unroll
        for (int st = 128; st > 0; st >>= 1) {
            if (tid < st) sred[tid] += sred[tid + st];
            __syncthreads();
        }
        if (tid == 0) {
            float d2sum = sred[0];
            float d1sum = 0.0f;
            #pragma unroll
            for (int t = 0; t < 32; t++) d1sum += g_rowsum[n * 32 + t];
            float mask = 0.0f;
            #pragma unroll
            for (int c = 0; c < 16; c++) mask += g_maskpart[n * 16 + c];
            float cost = 0.5f * (d1sum * (1.0f / P) + d2sum * (1.0f / P));
            if (mask >= 0.0f) s_total += cost;
        }
        __syncthreads();
    }
    if (tid == 0) out[0] = s_total * (1.0f / NOBJ);
}

// ---------------------------------------------------------------------------
extern "C" void kernel_launch(void* const* d_in, const int* in_sizes, int n_in,
                              void* d_out, int out_size) {
    const float* pt1 = reinterpret_cast<const float*>(d_in[0]);
    const float* pt2 = reinterpret_cast<const float*>(d_in[1]);
    float* out = reinterpret_cast<float*>(d_out);
    (void)in_sizes; (void)n_in; (void)out_size;

    k_init<<<256, 256>>>(pt2);
    dim3 grid(P / BM, NOBJ);     // (32, 16)
    k_main<<<grid, 256>>>(pt1, pt2);
    k_final<<<1, 256>>>(out);
}

// round 3
// speedup vs baseline: 1.5113x; 1.5113x over previous
#include <cuda_runtime.h>
#include <cuda_bf16.h>
#include <cstdint>

// Fixed shapes: [16, 4096, 2] fp32 both inputs
#define NOBJ 16
#define P    4096
#define BQ   128      // queries per CTA
#define BR   256      // refs staged per chunk
#define NCHUNK (P/BR)
#define EPSF 1e-12f

// Scratch (allocation-free): per-(n,tile) partial sums for each direction
static __device__ float g_sum1[NOBJ * 32];
static __device__ float g_sum2[NOBJ * 32];

// ---- packed fp32x2 helpers (FFMA2 is PTX-only; ptxas won't auto-fuse) ----
__device__ __forceinline__ unsigned long long pack2(float lo, float hi) {
    unsigned long long r;
    asm("mov.b64 %0, {%1, %2};" : "=l"(r) : "f"(lo), "f"(hi));
    return r;
}
__device__ __forceinline__ void unpack2(unsigned long long v, float& lo, float& hi) {
    asm("mov.b64 {%0, %1}, %2;" : "=f"(lo), "=f"(hi) : "l"(v));
}
__device__ __forceinline__ unsigned long long fma2(unsigned long long a,
                                                   unsigned long long b,
                                                   unsigned long long c) {
    unsigned long long d;
    asm("fma.rn.f32x2 %0, %1, %2, %3;" : "=l"(d) : "l"(a), "l"(b), "l"(c));
    return d;
}

// ---------------------------------------------------------------------------
// One-directional min pass: for each query point, min over ALL ref points of
//   u = |y|^2 - 2 x.y   (shift-invariant: d^2 = x2 + u)
// grid (32, 16), 256 threads. tx=tid&15 strides ref columns, ty=tid>>4 owns
// 8 queries packed as 4 f32x2 pairs. Refs staged in smem pre-duplicated as
// (v,v) u64 so the inner loop needs no packing: 3 LDS.64 + 8 FFMA2 + 8 FMNMX
// per 8 pairs.
// ---------------------------------------------------------------------------
__global__ __launch_bounds__(256) void k_pass(const float* __restrict__ q,
                                              const float* __restrict__ r,
                                              int dir) {
    const int n = blockIdx.y, tile = blockIdx.x, tid = threadIdx.x;
    const int tx = tid & 15, ty = tid >> 4;

    __shared__ unsigned long long sA[BR], sB[BR], sC[BR];
    __shared__ float2 sQ[BQ];
    __shared__ float  sRed[16];

    const float2* qp = reinterpret_cast<const float2*>(q) + n * P + tile * BQ;
    const float2* rp = reinterpret_cast<const float2*>(r) + n * P;

    if (tid < BQ) sQ[tid] = qp[tid];
    float2 ycur = rp[tid];               // prefetch chunk 0
    __syncthreads();

    unsigned long long m2a[4], m2b[4];
    float x2r[8], rmin[8];
    #pragma unroll
    for (int p = 0; p < 4; p++) {
        float2 xa = sQ[ty * 8 + 2 * p];
        float2 xb = sQ[ty * 8 + 2 * p + 1];
        m2a[p] = pack2(-2.0f * xa.x, -2.0f * xb.x);
        m2b[p] = pack2(-2.0f * xa.y, -2.0f * xb.y);
        x2r[2 * p]     = fmaf(xa.x, xa.x, xa.y * xa.y);
        x2r[2 * p + 1] = fmaf(xb.x, xb.x, xb.y * xb.y);
    }
    #pragma unroll
    for (int i = 0; i < 8; i++) rmin[i] = 3.402823466e38f;

    for (int jc = 0; jc < NCHUNK; jc++) {
        __syncthreads();                 // consumers done with previous chunk
        sA[tid] = pack2(ycur.x, ycur.x);
        sB[tid] = pack2(ycur.y, ycur.y);
        float yy = fmaf(ycur.x, ycur.x, ycur.y * ycur.y);
        sC[tid] = pack2(yy, yy);
        if (jc + 1 < NCHUNK) ycur = rp[(jc + 1) * BR + tid];  // overlap LDG with compute
        __syncthreads();

        #pragma unroll
        for (int jj = 0; jj < BR / 16; jj++) {
            const int c = jj * 16 + tx;  // 8B stride -> conflict-free / broadcast
            const unsigned long long ya = sA[c];
            const unsigned long long yb = sB[c];
            const unsigned long long yc = sC[c];
            #pragma unroll
            for (int p = 0; p < 4; p++) {
                unsigned long long u2 = fma2(m2a[p], ya, yc);
                u2 = fma2(m2b[p], yb, u2);
                float u0, u1;
                unpack2(u2, u0, u1);
                rmin[2 * p]     = fminf(rmin[2 * p], u0);
                rmin[2 * p + 1] = fminf(rmin[2 * p + 1], u1);
            }
        }
    }

    // min across the 16 tx lanes of each ty group (segmented shuffle width=16)
    float rs = 0.0f;
    #pragma unroll
    for (int i = 0; i < 8; i++) {
        float v = rmin[i];
        #pragma unroll
        for (int off = 8; off >= 1; off >>= 1)
            v = fminf(v, __shfl_xor_sync(0xffffffffu, v, off, 16));
        if (tx == 0) rs += sqrtf(fmaxf(x2r[i] + v, EPSF));
    }
    if (tx == 0) sRed[ty] = rs;
    __syncthreads();
    if (tid == 0) {
        float s = 0.0f;
        #pragma unroll
        for (int t = 0; t < 16; t++) s += sRed[t];
        (dir ? g_sum2 : g_sum1)[n * 32 + tile] = s;
    }
}

// ---------------------------------------------------------------------------
// Finalize: mask from set2 sums, combine directional sums, mean over objects.
// ---------------------------------------------------------------------------
__global__ void k_final(const float* __restrict__ pt2, float* __restrict__ out) {
    __shared__ float sred[256];
    const int tid = threadIdx.x;
    __shared__ float s_total;
    if (tid == 0) s_total = 0.0f;

    for (int n = 0; n < NOBJ; n++) {
        float s = 0.0f;
        const float* p = pt2 + n * P * 2;
        for (int i = tid; i < P * 2; i += 256) s += p[i];
        __syncthreads();
        sred[tid] = s;
        __syncthreads();
        #pragma unroll
        for (int st = 128; st > 0; st >>= 1) {
            if (tid < st) sred[tid] += sred[tid + st];
            __syncthreads();
        }
        if (tid == 0) {
            if (sred[0] >= 0.0f) {
                float s1 = 0.0f, s2 = 0.0f;
                #pragma unroll
                for (int t = 0; t < 32; t++) {
                    s1 += g_sum1[n * 32 + t];
                    s2 += g_sum2[n * 32 + t];
                }
                s_total += 0.5f * (s1 + s2) * (1.0f / P);
            }
        }
        __syncthreads();
    }
    if (tid == 0) out[0] = s_total * (1.0f / NOBJ);
}

// ---------------------------------------------------------------------------
extern "C" void kernel_launch(void* const* d_in, const int* in_sizes, int n_in,
                              void* d_out, int out_size) {
    const float* pt1 = reinterpret_cast<const float*>(d_in[0]);
    const float* pt2 = reinterpret_cast<const float*>(d_in[1]);
    float* out = reinterpret_cast<float*>(d_out);
    (void)in_sizes; (void)n_in; (void)out_size;

    dim3 grid(P / BQ, NOBJ);   // (32, 16)
    k_pass<<<grid, 256>>>(pt1, pt2, 0);   // d1: min over set2 for each set1 point
    k_pass<<<grid, 256>>>(pt2, pt1, 1);   // d2: min over set1 for each set2 point
    k_final<<<1, 256>>>(pt2, out);
}